// round 11
// baseline (speedup 1.0000x reference)
#include <cuda_runtime.h>

#define DEV __device__ __forceinline__
#define BIG 1.0e30f

__constant__ float c_mean[3] = {0.485f, 0.456f, 0.406f};
__constant__ float c_std[3]  = {0.229f, 0.224f, 0.225f};

DEV void cas(float &a, float &b) { float t = fminf(a, b); b = fmaxf(a, b); a = t; }

// 16-CAS sort of 7.
DEV void sort7(float* x) {
    cas(x[0], x[1]); cas(x[2], x[3]); cas(x[0], x[2]); cas(x[1], x[3]); cas(x[1], x[2]);
    cas(x[4], x[5]); cas(x[4], x[6]); cas(x[5], x[6]);
    cas(x[0], x[4]); cas(x[1], x[5]); cas(x[2], x[6]);
    cas(x[2], x[4]); cas(x[3], x[5]);
    cas(x[1], x[2]); cas(x[3], x[4]); cas(x[5], x[6]);
}

// Pruned Batcher merge of sorted a[7], b[7] -> sorted x[0..13]. 21 CAS.
DEV void merge77(const float* a, const float* b, float* x /*>=15*/) {
    #pragma unroll
    for (int i = 0; i < 7; ++i) x[i] = a[i];
    #pragma unroll
    for (int i = 0; i < 7; ++i) x[8 + i] = b[i];
    cas(x[0], x[8]); cas(x[1], x[9]); cas(x[2], x[10]); cas(x[3], x[11]);
    cas(x[4], x[12]); cas(x[5], x[13]); cas(x[6], x[14]);
    x[7] = x[11];
    cas(x[4], x[8]); cas(x[5], x[9]); cas(x[6], x[10]);
    cas(x[2], x[4]); cas(x[3], x[5]); cas(x[6], x[8]); cas(x[7], x[9]);
    cas(x[10], x[12]); x[11] = x[13];
    cas(x[1], x[2]); cas(x[3], x[4]); cas(x[5], x[6]); cas(x[7], x[8]);
    cas(x[9], x[10]); cas(x[11], x[12]); x[13] = x[14];
}

// Full merge of sorted x[0..13] (with x[14]=x[15]=BIG) and sorted x[16..29]
// -> M[0..27] in x[0..27]. 55 CAS + 6 renames.
DEV void mergeM(float* x) {
    cas(x[0], x[16]); cas(x[1], x[17]); cas(x[2], x[18]); cas(x[3], x[19]);
    cas(x[4], x[20]); cas(x[5], x[21]); cas(x[6], x[22]); cas(x[7], x[23]);
    cas(x[8], x[24]); cas(x[9], x[25]); cas(x[10], x[26]); cas(x[11], x[27]);
    cas(x[12], x[28]); cas(x[13], x[29]);
    cas(x[8], x[16]); cas(x[9], x[17]); cas(x[10], x[18]);
    cas(x[11], x[19]); cas(x[12], x[20]); cas(x[13], x[21]);
    x[14] = x[22]; x[15] = x[23];
    cas(x[4], x[8]); cas(x[5], x[9]); cas(x[6], x[10]); cas(x[7], x[11]);
    cas(x[12], x[16]); cas(x[13], x[17]); cas(x[14], x[18]); cas(x[15], x[19]);
    cas(x[20], x[24]); cas(x[21], x[25]);
    x[22] = x[26]; x[23] = x[27];
    cas(x[2], x[4]);  cas(x[3], x[5]);  cas(x[6], x[8]);  cas(x[7], x[9]);
    cas(x[10], x[12]); cas(x[11], x[13]); cas(x[14], x[16]); cas(x[15], x[17]);
    cas(x[18], x[20]); cas(x[19], x[21]); cas(x[22], x[24]); cas(x[23], x[25]);
    x[26] = x[28]; x[27] = x[29];
    cas(x[1], x[2]);  cas(x[3], x[4]);  cas(x[5], x[6]);  cas(x[7], x[8]);
    cas(x[9], x[10]); cas(x[11], x[12]); cas(x[13], x[14]); cas(x[15], x[16]);
    cas(x[17], x[18]); cas(x[19], x[20]); cas(x[21], x[22]); cas(x[23], x[24]);
    cas(x[25], x[26]);
}

// Pruned merge of M[0..27] (in x[0..27]) with sorted x[32..45],
// producing ONLY ranks 17..24 of the 42-merge in x[17..24]. 53 CAS.
DEV void mergeT(float* x) {
    cas(x[0], x[32]); cas(x[1], x[33]); cas(x[2], x[34]); cas(x[3], x[35]);
    cas(x[4], x[36]); cas(x[5], x[37]); cas(x[6], x[38]); cas(x[7], x[39]);
    cas(x[8], x[40]); cas(x[9], x[41]); cas(x[10], x[42]); cas(x[11], x[43]);
    cas(x[12], x[44]); cas(x[13], x[45]);
    cas(x[16], x[32]); cas(x[17], x[33]); cas(x[18], x[34]); cas(x[19], x[35]);
    cas(x[20], x[36]); cas(x[21], x[37]); cas(x[22], x[38]); cas(x[23], x[39]);
    cas(x[24], x[40]); cas(x[25], x[41]); cas(x[26], x[42]); cas(x[27], x[43]);
    cas(x[9], x[17]); cas(x[10], x[18]); cas(x[11], x[19]); cas(x[12], x[20]);
    cas(x[13], x[21]); cas(x[14], x[22]); cas(x[15], x[23]);
    cas(x[24], x[32]); cas(x[25], x[33]); cas(x[26], x[34]); cas(x[27], x[35]);
    cas(x[13], x[17]); cas(x[14], x[18]); cas(x[15], x[19]);
    cas(x[20], x[24]); cas(x[21], x[25]); cas(x[22], x[26]); cas(x[23], x[27]);
    cas(x[15], x[17]); cas(x[18], x[20]); cas(x[19], x[21]);
    cas(x[22], x[24]); cas(x[23], x[25]);
    cas(x[17], x[18]); cas(x[19], x[20]); cas(x[21], x[22]); cas(x[23], x[24]);
}

// med = rank 25 of T(42) U g(7) = min(T[24], min_j max(T[17+j], g[6-j])).
DEV float select25(const float* T, const float* g) {
    float c0 = fmaxf(T[17], g[6]);
    float c1 = fmaxf(T[18], g[5]);
    float c2 = fmaxf(T[19], g[4]);
    float c3 = fmaxf(T[20], g[3]);
    float c4 = fmaxf(T[21], g[2]);
    float c5 = fmaxf(T[22], g[1]);
    float c6 = fmaxf(T[23], g[0]);
    float c7 = T[24];
    return fminf(fminf(fminf(c0, c1), fminf(c2, c3)),
                 fminf(fminf(c4, c5), fminf(c6, c7)));
}

DEV void load_pair14(const float4 (*pb)[5], int m, float* dst) {
    float4 v0 = pb[m][0], v1 = pb[m][1], v2 = pb[m][2], v3 = pb[m][3];
    dst[0]=v0.x;  dst[1]=v0.y;  dst[2]=v0.z;   dst[3]=v0.w;
    dst[4]=v1.x;  dst[5]=v1.y;  dst[6]=v1.z;   dst[7]=v1.w;
    dst[8]=v2.x;  dst[9]=v2.y;  dst[10]=v2.z;  dst[11]=v2.w;
    dst[12]=v3.x; dst[13]=v3.y;
}

// x[0..27]=M sorted, x[32..45]=third pair: finish task u (pixels 2u-1, 2u).
DEV void task_finish(float* x, int u, const float (*srow)[518],
                     float* orow, float mean, float inv) {
    mergeT(x);
    {   // odd pixel 2u-1, lone sorted column smem 2u-1
        int gc = (2 * u - 1 < 0) ? 0 : 2 * u - 1;
        float g[7];
        #pragma unroll
        for (int d = 0; d < 7; ++d) g[d] = srow[d][gc];
        float med = select25(x, g);
        if (u >= 1) orow[2 * u - 1] = (med - mean) * inv;
    }
    {   // even pixel 2u, lone sorted column smem 2u+6
        int gc = (2 * u + 6 > 517) ? 517 : 2 * u + 6;
        float g[7];
        #pragma unroll
        for (int d = 0; d < 7; ++d) g[d] = srow[d][gc];
        float med = select25(x, g);
        if (u <= 255) orow[2 * u] = (med - mean) * inv;
    }
}

// One CTA = one output row; 256 threads. Producers (t<128) handle even tasks 2t,
// computing M=merge(pair 2t+1, pair 2t+2) shared with consumer t+128 (task 2t+1).
__global__ __launch_bounds__(256, 4) void median7_kernel(const float* __restrict__ img,
                                                         float* __restrict__ out) {
    const int y     = blockIdx.x;        // 0..511
    const int plane = blockIdx.y;        // 0..23
    const int ch    = plane % 3;
    const float mean = c_mean[ch];
    const float sd   = c_std[ch];

    __shared__ float  srow[7][518];      // rows -> sorted columns (in place)
    __shared__ float4 pairbuf[260][5];   // pair m: sorted 14 in [m][0..3]
    __shared__ float4 Mbuf[128][9];      // M_t: 28 floats in [t][0..6]; [9] pads banks

    const float* src = img + (size_t)plane * 262144;

    #pragma unroll
    for (int r = 0; r < 7; ++r) {
        int gy = y + r - 3;
        gy = (gy < 0) ? -gy : ((gy > 511) ? 1022 - gy : gy);
        const float* rp = src + gy * 512;
        for (int c = threadIdx.x; c < 518; c += 256) {
            int gx = c - 3;
            gx = (gx < 0) ? -gx : ((gx > 511) ? 1022 - gx : gx);
            float v = fmaf(rp[gx], sd, mean);
            srow[r][c] = fminf(fmaxf(v, 0.0f), 1.0f);
        }
    }
    __syncthreads();

    // Phase 1: task m owns smem columns 2m, 2m+1 exclusively (m < 259).
    for (int m = threadIdx.x; m < 259; m += 256) {
        float ca[7], cb[7], w[15];
        #pragma unroll
        for (int d = 0; d < 7; ++d) { ca[d] = srow[d][2 * m]; cb[d] = srow[d][2 * m + 1]; }
        sort7(ca); sort7(cb);
        #pragma unroll
        for (int d = 0; d < 7; ++d) { srow[d][2 * m] = ca[d]; srow[d][2 * m + 1] = cb[d]; }
        merge77(ca, cb, w);              // w[0..13] sorted
        pairbuf[m][0] = make_float4(w[0],  w[1],  w[2],  w[3]);
        pairbuf[m][1] = make_float4(w[4],  w[5],  w[6],  w[7]);
        pairbuf[m][2] = make_float4(w[8],  w[9],  w[10], w[11]);
        pairbuf[m][3] = make_float4(w[12], w[13], 0.0f,  0.0f);
    }
    __syncthreads();

    const float inv = 1.0f / sd;
    float* orow = out + (size_t)plane * 262144 + y * 512;
    const int t = threadIdx.x;

    float x[46];
    if (t < 128) {
        // Producer: task u=2t, triple {2t, 2t+1, 2t+2}; M = merge(2t+1, 2t+2).
        const int u = 2 * t;
        load_pair14(pairbuf, u + 1, x);
        x[14] = BIG; x[15] = BIG;
        load_pair14(pairbuf, u + 2, x + 16);
        mergeM(x);                       // x[0..27] = M
        Mbuf[t][0] = make_float4(x[0],  x[1],  x[2],  x[3]);
        Mbuf[t][1] = make_float4(x[4],  x[5],  x[6],  x[7]);
        Mbuf[t][2] = make_float4(x[8],  x[9],  x[10], x[11]);
        Mbuf[t][3] = make_float4(x[12], x[13], x[14], x[15]);
        Mbuf[t][4] = make_float4(x[16], x[17], x[18], x[19]);
        Mbuf[t][5] = make_float4(x[20], x[21], x[22], x[23]);
        Mbuf[t][6] = make_float4(x[24], x[25], x[26], x[27]);
        load_pair14(pairbuf, u, x + 32); // third = pair u
        task_finish(x, u, srow, orow, mean, inv);
    } else {
        // Consumer: prefetch third pair while producers work.
        load_pair14(pairbuf, 2 * (t - 128) + 3, x + 32);
    }
    __syncthreads();

    if (t < 128) {
        if (t == 0) {
            // Orphan task 256 (pixel 511): triple {256, 257, 258}.
            load_pair14(pairbuf, 257, x);
            x[14] = BIG; x[15] = BIG;
            load_pair14(pairbuf, 258, x + 16);
            mergeM(x);
            load_pair14(pairbuf, 256, x + 32);
            task_finish(x, 256, srow, orow, mean, inv);
        }
    } else {
        const int j = t - 128;           // task u = 2j+1, triple {2j+1, 2j+2, 2j+3}
        float4 v0 = Mbuf[j][0], v1 = Mbuf[j][1], v2 = Mbuf[j][2], v3 = Mbuf[j][3];
        float4 v4 = Mbuf[j][4], v5 = Mbuf[j][5], v6 = Mbuf[j][6];
        x[0]=v0.x;  x[1]=v0.y;  x[2]=v0.z;   x[3]=v0.w;
        x[4]=v1.x;  x[5]=v1.y;  x[6]=v1.z;   x[7]=v1.w;
        x[8]=v2.x;  x[9]=v2.y;  x[10]=v2.z;  x[11]=v2.w;
        x[12]=v3.x; x[13]=v3.y; x[14]=v3.z;  x[15]=v3.w;
        x[16]=v4.x; x[17]=v4.y; x[18]=v4.z;  x[19]=v4.w;
        x[20]=v5.x; x[21]=v5.y; x[22]=v5.z;  x[23]=v5.w;
        x[24]=v6.x; x[25]=v6.y; x[26]=v6.z;  x[27]=v6.w;
        task_finish(x, 2 * j + 1, srow, orow, mean, inv);
    }
}

extern "C" void kernel_launch(void* const* d_in, const int* in_sizes, int n_in,
                              void* d_out, int out_size) {
    const float* img  = (const float*)d_in[0];
    const float* mask = (const float*)d_in[1];
    float* out = (float*)d_out;
    const int img_elems  = in_sizes[0];
    const int mask_elems = in_sizes[1];

    dim3 grid(512, 24);
    median7_kernel<<<grid, 256>>>(img, out);
    cudaMemcpyAsync(out + img_elems, mask, (size_t)mask_elems * sizeof(float),
                    cudaMemcpyDeviceToDevice);
}

// round 13
// speedup vs baseline: 1.5799x; 1.5799x over previous
#include <cuda_runtime.h>

#define DEV __device__ __forceinline__
#define BIG 1.0e30f

__constant__ float c_mean[3] = {0.485f, 0.456f, 0.406f};
__constant__ float c_std[3]  = {0.229f, 0.224f, 0.225f};

DEV void cas(float &a, float &b) { float t = fminf(a, b); b = fmaxf(a, b); a = t; }

// 16-CAS sort of 7.
DEV void sort7(float* x) {
    cas(x[0], x[1]); cas(x[2], x[3]); cas(x[0], x[2]); cas(x[1], x[3]); cas(x[1], x[2]);
    cas(x[4], x[5]); cas(x[4], x[6]); cas(x[5], x[6]);
    cas(x[0], x[4]); cas(x[1], x[5]); cas(x[2], x[6]);
    cas(x[2], x[4]); cas(x[3], x[5]);
    cas(x[1], x[2]); cas(x[3], x[4]); cas(x[5], x[6]);
}

// Pruned Batcher merge of sorted a[7], b[7] -> sorted x[0..13]. 21 CAS.
DEV void merge77(const float* a, const float* b, float* x /*>=15*/) {
    #pragma unroll
    for (int i = 0; i < 7; ++i) x[i] = a[i];
    #pragma unroll
    for (int i = 0; i < 7; ++i) x[8 + i] = b[i];
    cas(x[0], x[8]); cas(x[1], x[9]); cas(x[2], x[10]); cas(x[3], x[11]);
    cas(x[4], x[12]); cas(x[5], x[13]); cas(x[6], x[14]);
    x[7] = x[11];
    cas(x[4], x[8]); cas(x[5], x[9]); cas(x[6], x[10]);
    cas(x[2], x[4]); cas(x[3], x[5]); cas(x[6], x[8]); cas(x[7], x[9]);
    cas(x[10], x[12]); x[11] = x[13];
    cas(x[1], x[2]); cas(x[3], x[4]); cas(x[5], x[6]); cas(x[7], x[8]);
    cas(x[9], x[10]); cas(x[11], x[12]); x[13] = x[14];
}

// Full merge of sorted x[0..13] (with x[14]=x[15]=BIG) and sorted x[16..29]
// -> M[0..27] in x[0..27]. 55 CAS + 6 renames.
DEV void mergeM(float* x) {
    cas(x[0], x[16]); cas(x[1], x[17]); cas(x[2], x[18]); cas(x[3], x[19]);
    cas(x[4], x[20]); cas(x[5], x[21]); cas(x[6], x[22]); cas(x[7], x[23]);
    cas(x[8], x[24]); cas(x[9], x[25]); cas(x[10], x[26]); cas(x[11], x[27]);
    cas(x[12], x[28]); cas(x[13], x[29]);
    cas(x[8], x[16]); cas(x[9], x[17]); cas(x[10], x[18]);
    cas(x[11], x[19]); cas(x[12], x[20]); cas(x[13], x[21]);
    x[14] = x[22]; x[15] = x[23];
    cas(x[4], x[8]); cas(x[5], x[9]); cas(x[6], x[10]); cas(x[7], x[11]);
    cas(x[12], x[16]); cas(x[13], x[17]); cas(x[14], x[18]); cas(x[15], x[19]);
    cas(x[20], x[24]); cas(x[21], x[25]);
    x[22] = x[26]; x[23] = x[27];
    cas(x[2], x[4]);  cas(x[3], x[5]);  cas(x[6], x[8]);  cas(x[7], x[9]);
    cas(x[10], x[12]); cas(x[11], x[13]); cas(x[14], x[16]); cas(x[15], x[17]);
    cas(x[18], x[20]); cas(x[19], x[21]); cas(x[22], x[24]); cas(x[23], x[25]);
    x[26] = x[28]; x[27] = x[29];
    cas(x[1], x[2]);  cas(x[3], x[4]);  cas(x[5], x[6]);  cas(x[7], x[8]);
    cas(x[9], x[10]); cas(x[11], x[12]); cas(x[13], x[14]); cas(x[15], x[16]);
    cas(x[17], x[18]); cas(x[19], x[20]); cas(x[21], x[22]); cas(x[23], x[24]);
    cas(x[25], x[26]);
}

// Pruned merge of M[0..27] (in x[0..27]) with sorted x[32..45],
// producing ONLY ranks 17..24 of the 42-merge in x[17..24]. 53 CAS.
DEV void mergeT(float* x) {
    cas(x[0], x[32]); cas(x[1], x[33]); cas(x[2], x[34]); cas(x[3], x[35]);
    cas(x[4], x[36]); cas(x[5], x[37]); cas(x[6], x[38]); cas(x[7], x[39]);
    cas(x[8], x[40]); cas(x[9], x[41]); cas(x[10], x[42]); cas(x[11], x[43]);
    cas(x[12], x[44]); cas(x[13], x[45]);
    cas(x[16], x[32]); cas(x[17], x[33]); cas(x[18], x[34]); cas(x[19], x[35]);
    cas(x[20], x[36]); cas(x[21], x[37]); cas(x[22], x[38]); cas(x[23], x[39]);
    cas(x[24], x[40]); cas(x[25], x[41]); cas(x[26], x[42]); cas(x[27], x[43]);
    cas(x[9], x[17]); cas(x[10], x[18]); cas(x[11], x[19]); cas(x[12], x[20]);
    cas(x[13], x[21]); cas(x[14], x[22]); cas(x[15], x[23]);
    cas(x[24], x[32]); cas(x[25], x[33]); cas(x[26], x[34]); cas(x[27], x[35]);
    cas(x[13], x[17]); cas(x[14], x[18]); cas(x[15], x[19]);
    cas(x[20], x[24]); cas(x[21], x[25]); cas(x[22], x[26]); cas(x[23], x[27]);
    cas(x[15], x[17]); cas(x[18], x[20]); cas(x[19], x[21]);
    cas(x[22], x[24]); cas(x[23], x[25]);
    cas(x[17], x[18]); cas(x[19], x[20]); cas(x[21], x[22]); cas(x[23], x[24]);
}

// med = rank 25 of T(42) U g(7) = min(T[24], min_j max(T[17+j], g[6-j])).
DEV float select25(const float* T, const float* g) {
    float c0 = fmaxf(T[17], g[6]);
    float c1 = fmaxf(T[18], g[5]);
    float c2 = fmaxf(T[19], g[4]);
    float c3 = fmaxf(T[20], g[3]);
    float c4 = fmaxf(T[21], g[2]);
    float c5 = fmaxf(T[22], g[1]);
    float c6 = fmaxf(T[23], g[0]);
    float c7 = T[24];
    return fminf(fminf(fminf(c0, c1), fminf(c2, c3)),
                 fminf(fminf(c4, c5), fminf(c6, c7)));
}

DEV void load_pair14(const float4 (*pb)[5], int m, float* dst) {
    float4 v0 = pb[m][0], v1 = pb[m][1], v2 = pb[m][2], v3 = pb[m][3];
    dst[0]=v0.x;  dst[1]=v0.y;  dst[2]=v0.z;   dst[3]=v0.w;
    dst[4]=v1.x;  dst[5]=v1.y;  dst[6]=v1.z;   dst[7]=v1.w;
    dst[8]=v2.x;  dst[9]=v2.y;  dst[10]=v2.z;  dst[11]=v2.w;
    dst[12]=v3.x; dst[13]=v3.y;
}

DEV float lone_med(const float* T, const float (*srow)[518], int col) {
    float g[7];
    #pragma unroll
    for (int d = 0; d < 7; ++d) g[d] = srow[d][col];
    return select25(T, g);
}

// One CTA = one output row; 128 threads x 4 px (2 tasks sharing one mergeM).
__global__ __launch_bounds__(128, 6) void median7_kernel(const float* __restrict__ img,
                                                         float* __restrict__ out) {
    const int y     = blockIdx.x;        // 0..511
    const int plane = blockIdx.y;        // 0..23
    const int ch    = plane % 3;
    const float mean = c_mean[ch];
    const float sd   = c_std[ch];

    __shared__ float  srow[7][518];      // rows -> sorted columns (in place)
    __shared__ float4 pairbuf[260][5];   // pair m: sorted 14 in [m][0..3]

    const float* src = img + (size_t)plane * 262144;

    #pragma unroll
    for (int r = 0; r < 7; ++r) {
        int gy = y + r - 3;
        gy = (gy < 0) ? -gy : ((gy > 511) ? 1022 - gy : gy);
        const float* rp = src + gy * 512;
        for (int c = threadIdx.x; c < 518; c += 128) {
            int gx = c - 3;
            gx = (gx < 0) ? -gx : ((gx > 511) ? 1022 - gx : gx);
            float v = fmaf(rp[gx], sd, mean);
            srow[r][c] = fminf(fmaxf(v, 0.0f), 1.0f);
        }
    }
    __syncthreads();

    // Phase 1: task m owns smem columns 2m, 2m+1 exclusively (m < 259).
    for (int m = threadIdx.x; m < 259; m += 128) {
        float ca[7], cb[7], w[15];
        #pragma unroll
        for (int d = 0; d < 7; ++d) { ca[d] = srow[d][2 * m]; cb[d] = srow[d][2 * m + 1]; }
        sort7(ca); sort7(cb);
        #pragma unroll
        for (int d = 0; d < 7; ++d) { srow[d][2 * m] = ca[d]; srow[d][2 * m + 1] = cb[d]; }
        merge77(ca, cb, w);              // w[0..13] sorted
        pairbuf[m][0] = make_float4(w[0],  w[1],  w[2],  w[3]);
        pairbuf[m][1] = make_float4(w[4],  w[5],  w[6],  w[7]);
        pairbuf[m][2] = make_float4(w[8],  w[9],  w[10], w[11]);
        pairbuf[m][3] = make_float4(w[12], w[13], 0.0f,  0.0f);
    }
    __syncthreads();

    const float inv = 1.0f / sd;
    float* orow = out + (size_t)plane * 262144 + y * 512;
    const int t = threadIdx.x;           // pixels 4t-1 .. 4t+2

    float x[46], M[28];

    // Shared M = merge(pair 2t+1, pair 2t+2), serves tasks u=2t and u=2t+1.
    load_pair14(pairbuf, 2 * t + 1, x);
    x[14] = BIG; x[15] = BIG;
    load_pair14(pairbuf, 2 * t + 2, x + 16);
    mergeM(x);                           // x[0..27] = M
    #pragma unroll
    for (int i = 0; i < 28; ++i) M[i] = x[i];

    // Task A: u=2t (pixels 4t-1, 4t), third = pair 2t.
    load_pair14(pairbuf, 2 * t, x + 32);
    mergeT(x);
    float mA0 = lone_med(x, srow, (t == 0) ? 0 : 4 * t - 1);  // odd px 4t-1
    float mA1 = lone_med(x, srow, 4 * t + 6);                 // even px 4t

    // Task B: u=2t+1 (pixels 4t+1, 4t+2), third = pair 2t+3.
    #pragma unroll
    for (int i = 0; i < 28; ++i) x[i] = M[i];
    load_pair14(pairbuf, 2 * t + 3, x + 32);
    mergeT(x);
    float mB0 = lone_med(x, srow, 4 * t + 1);                 // odd px 4t+1
    float mB1 = lone_med(x, srow, 4 * t + 8);                 // even px 4t+2

    if (t > 0) orow[4 * t - 1] = (mA0 - mean) * inv;
    float2 o01; o01.x = (mA1 - mean) * inv; o01.y = (mB0 - mean) * inv;
    *reinterpret_cast<float2*>(orow + 4 * t) = o01;
    orow[4 * t + 2] = (mB1 - mean) * inv;

    // Orphan pixel 511 (task u=256, odd pixel only) on thread 127.
    if (t == 127) {
        load_pair14(pairbuf, 257, x);
        x[14] = BIG; x[15] = BIG;
        load_pair14(pairbuf, 258, x + 16);
        mergeM(x);
        load_pair14(pairbuf, 256, x + 32);
        mergeT(x);
        float m511 = lone_med(x, srow, 511);
        orow[511] = (m511 - mean) * inv;
    }
}

extern "C" void kernel_launch(void* const* d_in, const int* in_sizes, int n_in,
                              void* d_out, int out_size) {
    const float* img  = (const float*)d_in[0];
    const float* mask = (const float*)d_in[1];
    float* out = (float*)d_out;
    const int img_elems  = in_sizes[0];
    const int mask_elems = in_sizes[1];

    dim3 grid(512, 24);
    median7_kernel<<<grid, 128>>>(img, out);
    cudaMemcpyAsync(out + img_elems, mask, (size_t)mask_elems * sizeof(float),
                    cudaMemcpyDeviceToDevice);
}

// round 14
// speedup vs baseline: 1.7330x; 1.0969x over previous
#include <cuda_runtime.h>

#define DEV __device__ __forceinline__
#define BIG 1.0e30f

__constant__ float c_mean[3] = {0.485f, 0.456f, 0.406f};
__constant__ float c_std[3]  = {0.229f, 0.224f, 0.225f};

DEV void cas(float &a, float &b) { float t = fminf(a, b); b = fmaxf(a, b); a = t; }

// 16-CAS sort of 7.
DEV void sort7(float* x) {
    cas(x[0], x[1]); cas(x[2], x[3]); cas(x[0], x[2]); cas(x[1], x[3]); cas(x[1], x[2]);
    cas(x[4], x[5]); cas(x[4], x[6]); cas(x[5], x[6]);
    cas(x[0], x[4]); cas(x[1], x[5]); cas(x[2], x[6]);
    cas(x[2], x[4]); cas(x[3], x[5]);
    cas(x[1], x[2]); cas(x[3], x[4]); cas(x[5], x[6]);
}

// Pruned Batcher merge of sorted a[7], b[7] -> sorted x[0..13]. 21 CAS.
DEV void merge77(const float* a, const float* b, float* x /*>=15*/) {
    #pragma unroll
    for (int i = 0; i < 7; ++i) x[i] = a[i];
    #pragma unroll
    for (int i = 0; i < 7; ++i) x[8 + i] = b[i];
    cas(x[0], x[8]); cas(x[1], x[9]); cas(x[2], x[10]); cas(x[3], x[11]);
    cas(x[4], x[12]); cas(x[5], x[13]); cas(x[6], x[14]);
    x[7] = x[11];
    cas(x[4], x[8]); cas(x[5], x[9]); cas(x[6], x[10]);
    cas(x[2], x[4]); cas(x[3], x[5]); cas(x[6], x[8]); cas(x[7], x[9]);
    cas(x[10], x[12]); x[11] = x[13];
    cas(x[1], x[2]); cas(x[3], x[4]); cas(x[5], x[6]); cas(x[7], x[8]);
    cas(x[9], x[10]); cas(x[11], x[12]); x[13] = x[14];
}

// Full merge of sorted x[0..13] (with x[14]=x[15]=BIG) and sorted x[16..29]
// -> M[0..27] in x[0..27]. 55 CAS + 6 renames.
DEV void mergeM(float* x) {
    cas(x[0], x[16]); cas(x[1], x[17]); cas(x[2], x[18]); cas(x[3], x[19]);
    cas(x[4], x[20]); cas(x[5], x[21]); cas(x[6], x[22]); cas(x[7], x[23]);
    cas(x[8], x[24]); cas(x[9], x[25]); cas(x[10], x[26]); cas(x[11], x[27]);
    cas(x[12], x[28]); cas(x[13], x[29]);
    cas(x[8], x[16]); cas(x[9], x[17]); cas(x[10], x[18]);
    cas(x[11], x[19]); cas(x[12], x[20]); cas(x[13], x[21]);
    x[14] = x[22]; x[15] = x[23];
    cas(x[4], x[8]); cas(x[5], x[9]); cas(x[6], x[10]); cas(x[7], x[11]);
    cas(x[12], x[16]); cas(x[13], x[17]); cas(x[14], x[18]); cas(x[15], x[19]);
    cas(x[20], x[24]); cas(x[21], x[25]);
    x[22] = x[26]; x[23] = x[27];
    cas(x[2], x[4]);  cas(x[3], x[5]);  cas(x[6], x[8]);  cas(x[7], x[9]);
    cas(x[10], x[12]); cas(x[11], x[13]); cas(x[14], x[16]); cas(x[15], x[17]);
    cas(x[18], x[20]); cas(x[19], x[21]); cas(x[22], x[24]); cas(x[23], x[25]);
    x[26] = x[28]; x[27] = x[29];
    cas(x[1], x[2]);  cas(x[3], x[4]);  cas(x[5], x[6]);  cas(x[7], x[8]);
    cas(x[9], x[10]); cas(x[11], x[12]); cas(x[13], x[14]); cas(x[15], x[16]);
    cas(x[17], x[18]); cas(x[19], x[20]); cas(x[21], x[22]); cas(x[23], x[24]);
    cas(x[25], x[26]);
}

// Pruned merge of M[0..27] (in x[0..27]) with sorted x[32..45],
// producing ONLY ranks 17..24 of the 42-merge in x[17..24].
// First-pass mins x[0..8] are dead -> max-only. 44 CAS + 9 MAX = 97 FMNMX.
DEV void mergeT(float* x) {
    // K=32: i=0..8 max-only (min result never read), i=9..13 full CAS
    x[32] = fmaxf(x[0], x[32]); x[33] = fmaxf(x[1], x[33]);
    x[34] = fmaxf(x[2], x[34]); x[35] = fmaxf(x[3], x[35]);
    x[36] = fmaxf(x[4], x[36]); x[37] = fmaxf(x[5], x[37]);
    x[38] = fmaxf(x[6], x[38]); x[39] = fmaxf(x[7], x[39]);
    x[40] = fmaxf(x[8], x[40]);
    cas(x[9], x[41]); cas(x[10], x[42]); cas(x[11], x[43]);
    cas(x[12], x[44]); cas(x[13], x[45]);
    // K=16
    cas(x[16], x[32]); cas(x[17], x[33]); cas(x[18], x[34]); cas(x[19], x[35]);
    cas(x[20], x[36]); cas(x[21], x[37]); cas(x[22], x[38]); cas(x[23], x[39]);
    cas(x[24], x[40]); cas(x[25], x[41]); cas(x[26], x[42]); cas(x[27], x[43]);
    // K=8 (cone)
    cas(x[9], x[17]); cas(x[10], x[18]); cas(x[11], x[19]); cas(x[12], x[20]);
    cas(x[13], x[21]); cas(x[14], x[22]); cas(x[15], x[23]);
    cas(x[24], x[32]); cas(x[25], x[33]); cas(x[26], x[34]); cas(x[27], x[35]);
    // K=4 (cone)
    cas(x[13], x[17]); cas(x[14], x[18]); cas(x[15], x[19]);
    cas(x[20], x[24]); cas(x[21], x[25]); cas(x[22], x[26]); cas(x[23], x[27]);
    // K=2 (cone)
    cas(x[15], x[17]); cas(x[18], x[20]); cas(x[19], x[21]);
    cas(x[22], x[24]); cas(x[23], x[25]);
    // K=1 (cone)
    cas(x[17], x[18]); cas(x[19], x[20]); cas(x[21], x[22]); cas(x[23], x[24]);
}

// med = rank 25 of T(42) U g(7) = min(T[24], min_j max(T[17+j], g[6-j])).
DEV float select25(const float* T, const float* g) {
    float c0 = fmaxf(T[17], g[6]);
    float c1 = fmaxf(T[18], g[5]);
    float c2 = fmaxf(T[19], g[4]);
    float c3 = fmaxf(T[20], g[3]);
    float c4 = fmaxf(T[21], g[2]);
    float c5 = fmaxf(T[22], g[1]);
    float c6 = fmaxf(T[23], g[0]);
    float c7 = T[24];
    return fminf(fminf(fminf(c0, c1), fminf(c2, c3)),
                 fminf(fminf(c4, c5), fminf(c6, c7)));
}

DEV void load_pair14(const float4 (*pb)[5], int m, float* dst) {
    float4 v0 = pb[m][0], v1 = pb[m][1], v2 = pb[m][2], v3 = pb[m][3];
    dst[0]=v0.x;  dst[1]=v0.y;  dst[2]=v0.z;   dst[3]=v0.w;
    dst[4]=v1.x;  dst[5]=v1.y;  dst[6]=v1.z;   dst[7]=v1.w;
    dst[8]=v2.x;  dst[9]=v2.y;  dst[10]=v2.z;  dst[11]=v2.w;
    dst[12]=v3.x; dst[13]=v3.y;
}

// One CTA = one output row of one (b,c) plane; 256 threads, 257 tasks x 2 px.
__global__ __launch_bounds__(256, 5) void median7_kernel(const float* __restrict__ img,
                                                         float* __restrict__ out) {
    const int y     = blockIdx.x;        // 0..511
    const int plane = blockIdx.y;        // 0..23
    const int ch    = plane % 3;
    const float mean = c_mean[ch];
    const float sd   = c_std[ch];

    __shared__ float  srow[7][518];      // rows -> sorted columns (in place)
    __shared__ float4 pairbuf[260][5];   // pair m: sorted 14 in [m][0..3]

    const float* src = img + (size_t)plane * 262144;

    #pragma unroll
    for (int r = 0; r < 7; ++r) {
        int gy = y + r - 3;
        gy = (gy < 0) ? -gy : ((gy > 511) ? 1022 - gy : gy);
        const float* rp = src + gy * 512;
        for (int c = threadIdx.x; c < 518; c += 256) {
            int gx = c - 3;
            gx = (gx < 0) ? -gx : ((gx > 511) ? 1022 - gx : gx);
            float v = fmaf(rp[gx], sd, mean);
            srow[r][c] = fminf(fmaxf(v, 0.0f), 1.0f);
        }
    }
    __syncthreads();

    // Phase 1: task m owns smem columns 2m, 2m+1 exclusively (m < 259).
    for (int m = threadIdx.x; m < 259; m += 256) {
        float ca[7], cb[7], w[15];
        #pragma unroll
        for (int d = 0; d < 7; ++d) { ca[d] = srow[d][2 * m]; cb[d] = srow[d][2 * m + 1]; }
        sort7(ca); sort7(cb);
        #pragma unroll
        for (int d = 0; d < 7; ++d) { srow[d][2 * m] = ca[d]; srow[d][2 * m + 1] = cb[d]; }
        merge77(ca, cb, w);              // w[0..13] sorted
        pairbuf[m][0] = make_float4(w[0],  w[1],  w[2],  w[3]);
        pairbuf[m][1] = make_float4(w[4],  w[5],  w[6],  w[7]);
        pairbuf[m][2] = make_float4(w[8],  w[9],  w[10], w[11]);
        pairbuf[m][3] = make_float4(w[12], w[13], 0.0f,  0.0f);
    }
    __syncthreads();

    const float inv = 1.0f / sd;
    float* orow = out + (size_t)plane * 262144 + y * 512;

    // Phase 2: task u covers pixels at global cols (2u-1, 2u); both share the
    // pair triple {u, u+1, u+2}. u=0 emits only col 0; u=256 only col 511.
    for (int u = threadIdx.x; u <= 256; u += 256) {
        float x[46];
        load_pair14(pairbuf, u, x);
        x[14] = BIG; x[15] = BIG;
        load_pair14(pairbuf, u + 1, x + 16);
        mergeM(x);                       // x[0..27] = sorted 28
        load_pair14(pairbuf, u + 2, x + 32);
        mergeT(x);                       // x[17..24] = T[17..24]

        {   // odd pixel: global col 2u-1, lone sorted column smem 2u-1
            int gc = (2 * u - 1 < 0) ? 0 : 2 * u - 1;
            float g[7];
            #pragma unroll
            for (int d = 0; d < 7; ++d) g[d] = srow[d][gc];
            float med = select25(x, g);
            if (u >= 1) orow[2 * u - 1] = (med - mean) * inv;
        }
        {   // even pixel: global col 2u, lone sorted column smem 2u+6
            int gc = (2 * u + 6 > 517) ? 517 : 2 * u + 6;
            float g[7];
            #pragma unroll
            for (int d = 0; d < 7; ++d) g[d] = srow[d][gc];
            float med = select25(x, g);
            if (u <= 255) orow[2 * u] = (med - mean) * inv;
        }
    }
}

extern "C" void kernel_launch(void* const* d_in, const int* in_sizes, int n_in,
                              void* d_out, int out_size) {
    const float* img  = (const float*)d_in[0];
    const float* mask = (const float*)d_in[1];
    float* out = (float*)d_out;
    const int img_elems  = in_sizes[0];
    const int mask_elems = in_sizes[1];

    dim3 grid(512, 24);
    median7_kernel<<<grid, 256>>>(img, out);
    cudaMemcpyAsync(out + img_elems, mask, (size_t)mask_elems * sizeof(float),
                    cudaMemcpyDeviceToDevice);
}

// round 16
// speedup vs baseline: 1.7573x; 1.0140x over previous
#include <cuda_runtime.h>

#define DEV __device__ __forceinline__
#define BIG 1.0e30f

__constant__ float c_mean[3] = {0.485f, 0.456f, 0.406f};
__constant__ float c_std[3]  = {0.229f, 0.224f, 0.225f};

DEV void cas(float &a, float &b) { float t = fminf(a, b); b = fmaxf(a, b); a = t; }

// 16-CAS sort of 7.
DEV void sort7(float* x) {
    cas(x[0], x[1]); cas(x[2], x[3]); cas(x[0], x[2]); cas(x[1], x[3]); cas(x[1], x[2]);
    cas(x[4], x[5]); cas(x[4], x[6]); cas(x[5], x[6]);
    cas(x[0], x[4]); cas(x[1], x[5]); cas(x[2], x[6]);
    cas(x[2], x[4]); cas(x[3], x[5]);
    cas(x[1], x[2]); cas(x[3], x[4]); cas(x[5], x[6]);
}

// Pruned Batcher merge of sorted a[7], b[7] -> sorted x[0..13]. 21 CAS.
DEV void merge77(const float* a, const float* b, float* x /*>=15*/) {
    #pragma unroll
    for (int i = 0; i < 7; ++i) x[i] = a[i];
    #pragma unroll
    for (int i = 0; i < 7; ++i) x[8 + i] = b[i];
    cas(x[0], x[8]); cas(x[1], x[9]); cas(x[2], x[10]); cas(x[3], x[11]);
    cas(x[4], x[12]); cas(x[5], x[13]); cas(x[6], x[14]);
    x[7] = x[11];
    cas(x[4], x[8]); cas(x[5], x[9]); cas(x[6], x[10]);
    cas(x[2], x[4]); cas(x[3], x[5]); cas(x[6], x[8]); cas(x[7], x[9]);
    cas(x[10], x[12]); x[11] = x[13];
    cas(x[1], x[2]); cas(x[3], x[4]); cas(x[5], x[6]); cas(x[7], x[8]);
    cas(x[9], x[10]); cas(x[11], x[12]); x[13] = x[14];
}

// Full merge of sorted x[0..13] (with x[14]=x[15]=BIG) and sorted x[16..29]
// -> M[0..27] in x[0..27]. 55 CAS + 6 renames.
DEV void mergeM(float* x) {
    cas(x[0], x[16]); cas(x[1], x[17]); cas(x[2], x[18]); cas(x[3], x[19]);
    cas(x[4], x[20]); cas(x[5], x[21]); cas(x[6], x[22]); cas(x[7], x[23]);
    cas(x[8], x[24]); cas(x[9], x[25]); cas(x[10], x[26]); cas(x[11], x[27]);
    cas(x[12], x[28]); cas(x[13], x[29]);
    cas(x[8], x[16]); cas(x[9], x[17]); cas(x[10], x[18]);
    cas(x[11], x[19]); cas(x[12], x[20]); cas(x[13], x[21]);
    x[14] = x[22]; x[15] = x[23];
    cas(x[4], x[8]); cas(x[5], x[9]); cas(x[6], x[10]); cas(x[7], x[11]);
    cas(x[12], x[16]); cas(x[13], x[17]); cas(x[14], x[18]); cas(x[15], x[19]);
    cas(x[20], x[24]); cas(x[21], x[25]);
    x[22] = x[26]; x[23] = x[27];
    cas(x[2], x[4]);  cas(x[3], x[5]);  cas(x[6], x[8]);  cas(x[7], x[9]);
    cas(x[10], x[12]); cas(x[11], x[13]); cas(x[14], x[16]); cas(x[15], x[17]);
    cas(x[18], x[20]); cas(x[19], x[21]); cas(x[22], x[24]); cas(x[23], x[25]);
    x[26] = x[28]; x[27] = x[29];
    cas(x[1], x[2]);  cas(x[3], x[4]);  cas(x[5], x[6]);  cas(x[7], x[8]);
    cas(x[9], x[10]); cas(x[11], x[12]); cas(x[13], x[14]); cas(x[15], x[16]);
    cas(x[17], x[18]); cas(x[19], x[20]); cas(x[21], x[22]); cas(x[23], x[24]);
    cas(x[25], x[26]);
}

// Pruned merge of M[0..27] (in x[0..27]) with sorted x[32..45],
// producing ONLY ranks 17..24 of the 42-merge in x[17..24].
// First-pass mins x[0..8] are dead -> max-only. 44 CAS + 9 MAX = 97 FMNMX.
DEV void mergeT(float* x) {
    // K=32: i=0..8 max-only (min result never read), i=9..13 full CAS
    x[32] = fmaxf(x[0], x[32]); x[33] = fmaxf(x[1], x[33]);
    x[34] = fmaxf(x[2], x[34]); x[35] = fmaxf(x[3], x[35]);
    x[36] = fmaxf(x[4], x[36]); x[37] = fmaxf(x[5], x[37]);
    x[38] = fmaxf(x[6], x[38]); x[39] = fmaxf(x[7], x[39]);
    x[40] = fmaxf(x[8], x[40]);
    cas(x[9], x[41]); cas(x[10], x[42]); cas(x[11], x[43]);
    cas(x[12], x[44]); cas(x[13], x[45]);
    // K=16
    cas(x[16], x[32]); cas(x[17], x[33]); cas(x[18], x[34]); cas(x[19], x[35]);
    cas(x[20], x[36]); cas(x[21], x[37]); cas(x[22], x[38]); cas(x[23], x[39]);
    cas(x[24], x[40]); cas(x[25], x[41]); cas(x[26], x[42]); cas(x[27], x[43]);
    // K=8 (cone)
    cas(x[9], x[17]); cas(x[10], x[18]); cas(x[11], x[19]); cas(x[12], x[20]);
    cas(x[13], x[21]); cas(x[14], x[22]); cas(x[15], x[23]);
    cas(x[24], x[32]); cas(x[25], x[33]); cas(x[26], x[34]); cas(x[27], x[35]);
    // K=4 (cone)
    cas(x[13], x[17]); cas(x[14], x[18]); cas(x[15], x[19]);
    cas(x[20], x[24]); cas(x[21], x[25]); cas(x[22], x[26]); cas(x[23], x[27]);
    // K=2 (cone)
    cas(x[15], x[17]); cas(x[18], x[20]); cas(x[19], x[21]);
    cas(x[22], x[24]); cas(x[23], x[25]);
    // K=1 (cone)
    cas(x[17], x[18]); cas(x[19], x[20]); cas(x[21], x[22]); cas(x[23], x[24]);
}

// med = rank 25 of T(42) U g(7) = min(T[24], min_j max(T[17+j], g[6-j])).
DEV float select25(const float* T, const float* g) {
    float c0 = fmaxf(T[17], g[6]);
    float c1 = fmaxf(T[18], g[5]);
    float c2 = fmaxf(T[19], g[4]);
    float c3 = fmaxf(T[20], g[3]);
    float c4 = fmaxf(T[21], g[2]);
    float c5 = fmaxf(T[22], g[1]);
    float c6 = fmaxf(T[23], g[0]);
    float c7 = T[24];
    return fminf(fminf(fminf(c0, c1), fminf(c2, c3)),
                 fminf(fminf(c4, c5), fminf(c6, c7)));
}

DEV void load_pair14(const float4 (*pb)[5], int m, float* dst) {
    float4 v0 = pb[m][0], v1 = pb[m][1], v2 = pb[m][2], v3 = pb[m][3];
    dst[0]=v0.x;  dst[1]=v0.y;  dst[2]=v0.z;   dst[3]=v0.w;
    dst[4]=v1.x;  dst[5]=v1.y;  dst[6]=v1.z;   dst[7]=v1.w;
    dst[8]=v2.x;  dst[9]=v2.y;  dst[10]=v2.z;  dst[11]=v2.w;
    dst[12]=v3.x; dst[13]=v3.y;
}

// One CTA = one output row of one (b,c) plane; 256 threads, 257 tasks x 2 px.
__global__ __launch_bounds__(256, 6) void median7_kernel(const float* __restrict__ img,
                                                         float* __restrict__ out) {
    const int y     = blockIdx.x;        // 0..511
    const int plane = blockIdx.y;        // 0..23
    const int ch    = plane % 3;
    const float mean = c_mean[ch];
    const float sd   = c_std[ch];

    __shared__ float  srow[7][518];      // rows -> sorted columns (in place)
    __shared__ float4 pairbuf[260][5];   // pair m: sorted 14 in [m][0..3]

    const float* src = img + (size_t)plane * 262144;

    #pragma unroll
    for (int r = 0; r < 7; ++r) {
        int gy = y + r - 3;
        gy = (gy < 0) ? -gy : ((gy > 511) ? 1022 - gy : gy);
        const float* rp = src + gy * 512;
        for (int c = threadIdx.x; c < 518; c += 256) {
            int gx = c - 3;
            gx = (gx < 0) ? -gx : ((gx > 511) ? 1022 - gx : gx);
            float v = fmaf(rp[gx], sd, mean);
            srow[r][c] = fminf(fmaxf(v, 0.0f), 1.0f);
        }
    }
    __syncthreads();

    // Phase 1: task m owns smem columns 2m, 2m+1 exclusively (m < 259).
    for (int m = threadIdx.x; m < 259; m += 256) {
        float ca[7], cb[7], w[15];
        #pragma unroll
        for (int d = 0; d < 7; ++d) { ca[d] = srow[d][2 * m]; cb[d] = srow[d][2 * m + 1]; }
        sort7(ca); sort7(cb);
        #pragma unroll
        for (int d = 0; d < 7; ++d) { srow[d][2 * m] = ca[d]; srow[d][2 * m + 1] = cb[d]; }
        merge77(ca, cb, w);              // w[0..13] sorted
        pairbuf[m][0] = make_float4(w[0],  w[1],  w[2],  w[3]);
        pairbuf[m][1] = make_float4(w[4],  w[5],  w[6],  w[7]);
        pairbuf[m][2] = make_float4(w[8],  w[9],  w[10], w[11]);
        pairbuf[m][3] = make_float4(w[12], w[13], 0.0f,  0.0f);
    }
    __syncthreads();

    const float inv = 1.0f / sd;
    float* orow = out + (size_t)plane * 262144 + y * 512;

    // Phase 2: task u covers pixels at global cols (2u-1, 2u); both share the
    // pair triple {u, u+1, u+2}. u=0 emits only col 0; u=256 only col 511.
    for (int u = threadIdx.x; u <= 256; u += 256) {
        float x[46];
        load_pair14(pairbuf, u, x);
        x[14] = BIG; x[15] = BIG;
        load_pair14(pairbuf, u + 1, x + 16);
        mergeM(x);                       // x[0..27] = sorted 28
        load_pair14(pairbuf, u + 2, x + 32);
        mergeT(x);                       // x[17..24] = T[17..24]

        {   // odd pixel: global col 2u-1, lone sorted column smem 2u-1
            int gc = (2 * u - 1 < 0) ? 0 : 2 * u - 1;
            float g[7];
            #pragma unroll
            for (int d = 0; d < 7; ++d) g[d] = srow[d][gc];
            float med = select25(x, g);
            if (u >= 1) orow[2 * u - 1] = (med - mean) * inv;
        }
        {   // even pixel: global col 2u, lone sorted column smem 2u+6
            int gc = (2 * u + 6 > 517) ? 517 : 2 * u + 6;
            float g[7];
            #pragma unroll
            for (int d = 0; d < 7; ++d) g[d] = srow[d][gc];
            float med = select25(x, g);
            if (u <= 255) orow[2 * u] = (med - mean) * inv;
        }
    }
}

extern "C" void kernel_launch(void* const* d_in, const int* in_sizes, int n_in,
                              void* d_out, int out_size) {
    const float* img  = (const float*)d_in[0];
    const float* mask = (const float*)d_in[1];
    float* out = (float*)d_out;
    const int img_elems  = in_sizes[0];
    const int mask_elems = in_sizes[1];

    dim3 grid(512, 24);
    median7_kernel<<<grid, 256>>>(img, out);
    cudaMemcpyAsync(out + img_elems, mask, (size_t)mask_elems * sizeof(float),
                    cudaMemcpyDeviceToDevice);
}

// round 17
// speedup vs baseline: 1.8786x; 1.0690x over previous
#include <cuda_runtime.h>

#define DEV __device__ __forceinline__

__constant__ float c_mean[3] = {0.485f, 0.456f, 0.406f};
__constant__ float c_std[3]  = {0.229f, 0.224f, 0.225f};

DEV void cas(float &a, float &b) { float t = fminf(a, b); b = fmaxf(a, b); a = t; }

// 16-CAS sort of 7.
DEV void sort7(float* x) {
    cas(x[0], x[1]); cas(x[2], x[3]); cas(x[0], x[2]); cas(x[1], x[3]); cas(x[1], x[2]);
    cas(x[4], x[5]); cas(x[4], x[6]); cas(x[5], x[6]);
    cas(x[0], x[4]); cas(x[1], x[5]); cas(x[2], x[6]);
    cas(x[2], x[4]); cas(x[3], x[5]);
    cas(x[1], x[2]); cas(x[3], x[4]); cas(x[5], x[6]);
}

// Pruned Batcher merge of sorted a[7], b[7] -> sorted x[0..13]. 21 CAS.
DEV void merge77(const float* a, const float* b, float* x /*>=15*/) {
    #pragma unroll
    for (int i = 0; i < 7; ++i) x[i] = a[i];
    #pragma unroll
    for (int i = 0; i < 7; ++i) x[8 + i] = b[i];
    cas(x[0], x[8]); cas(x[1], x[9]); cas(x[2], x[10]); cas(x[3], x[11]);
    cas(x[4], x[12]); cas(x[5], x[13]); cas(x[6], x[14]);
    x[7] = x[11];
    cas(x[4], x[8]); cas(x[5], x[9]); cas(x[6], x[10]);
    cas(x[2], x[4]); cas(x[3], x[5]); cas(x[6], x[8]); cas(x[7], x[9]);
    cas(x[10], x[12]); x[11] = x[13];
    cas(x[1], x[2]); cas(x[3], x[4]); cas(x[5], x[6]); cas(x[7], x[8]);
    cas(x[9], x[10]); cas(x[11], x[12]); x[13] = x[14];
}

// Merge of sorted x[0..13] and sorted x[16..29], producing ONLY ranks 3..24 of
// the 28-merge valid in x[3..24] (mergeT never reads M[0..2], M[25..27]).
// Inputs x[14],x[15] are never read. 47 CAS + 6 single MIN/MAX = 100 FMNMX.
DEV void mergeM(float* x) {
    // K=16: i=0,1 max-only; i=2..11 full CAS; i=12,13 min-only
    x[16] = fmaxf(x[0], x[16]); x[17] = fmaxf(x[1], x[17]);
    cas(x[2], x[18]); cas(x[3], x[19]);
    cas(x[4], x[20]); cas(x[5], x[21]); cas(x[6], x[22]); cas(x[7], x[23]);
    cas(x[8], x[24]); cas(x[9], x[25]); cas(x[10], x[26]); cas(x[11], x[27]);
    x[12] = fminf(x[12], x[28]); x[13] = fminf(x[13], x[29]);
    // K=8
    cas(x[8], x[16]); cas(x[9], x[17]); cas(x[10], x[18]);
    cas(x[11], x[19]); cas(x[12], x[20]); cas(x[13], x[21]);
    x[14] = x[22]; x[15] = x[23];
    // K=4
    cas(x[4], x[8]); cas(x[5], x[9]); cas(x[6], x[10]); cas(x[7], x[11]);
    cas(x[12], x[16]); cas(x[13], x[17]); cas(x[14], x[18]); cas(x[15], x[19]);
    cas(x[20], x[24]); cas(x[21], x[25]);
    x[22] = x[26]; x[23] = x[27];
    // K=2: (2,4) max-only; (23,25) min-only; rest full CAS
    x[4] = fmaxf(x[2], x[4]);
    cas(x[3], x[5]);  cas(x[6], x[8]);  cas(x[7], x[9]);
    cas(x[10], x[12]); cas(x[11], x[13]); cas(x[14], x[16]); cas(x[15], x[17]);
    cas(x[18], x[20]); cas(x[19], x[21]); cas(x[22], x[24]);
    x[23] = fminf(x[23], x[25]);
    // K=1: drop (1,2) and (25,26) (outputs dead)
    cas(x[3], x[4]);  cas(x[5], x[6]);  cas(x[7], x[8]);  cas(x[9], x[10]);
    cas(x[11], x[12]); cas(x[13], x[14]); cas(x[15], x[16]); cas(x[17], x[18]);
    cas(x[19], x[20]); cas(x[21], x[22]); cas(x[23], x[24]);
}

// Pruned merge of M (x[3..24] valid) with sorted x[32..45], producing ONLY
// ranks 17..24 of the 42-merge in x[17..24].
// Rank bound: M[i] has rank in [i, i+14] -> M[0..2], M[25..27] irrelevant
// (treated as -inf/+inf: first-pass maxes dropped, K=16 CAS -> renames).
// 41 CAS + 6 MAX = 88 FMNMX.
DEV void mergeT(float* x) {
    // K=32: i=3..8 max-only; i=9..13 full CAS
    x[35] = fmaxf(x[3], x[35]);
    x[36] = fmaxf(x[4], x[36]); x[37] = fmaxf(x[5], x[37]);
    x[38] = fmaxf(x[6], x[38]); x[39] = fmaxf(x[7], x[39]);
    x[40] = fmaxf(x[8], x[40]);
    cas(x[9], x[41]); cas(x[10], x[42]); cas(x[11], x[43]);
    cas(x[12], x[44]); cas(x[13], x[45]);
    // K=16: i=0..8 CAS; i=9..11 renames (M[25..27] = +inf)
    cas(x[16], x[32]); cas(x[17], x[33]); cas(x[18], x[34]); cas(x[19], x[35]);
    cas(x[20], x[36]); cas(x[21], x[37]); cas(x[22], x[38]); cas(x[23], x[39]);
    cas(x[24], x[40]);
    x[25] = x[41]; x[26] = x[42]; x[27] = x[43];
    // K=8 (cone)
    cas(x[9], x[17]); cas(x[10], x[18]); cas(x[11], x[19]); cas(x[12], x[20]);
    cas(x[13], x[21]); cas(x[14], x[22]); cas(x[15], x[23]);
    cas(x[24], x[32]); cas(x[25], x[33]); cas(x[26], x[34]); cas(x[27], x[35]);
    // K=4 (cone)
    cas(x[13], x[17]); cas(x[14], x[18]); cas(x[15], x[19]);
    cas(x[20], x[24]); cas(x[21], x[25]); cas(x[22], x[26]); cas(x[23], x[27]);
    // K=2 (cone)
    cas(x[15], x[17]); cas(x[18], x[20]); cas(x[19], x[21]);
    cas(x[22], x[24]); cas(x[23], x[25]);
    // K=1 (cone)
    cas(x[17], x[18]); cas(x[19], x[20]); cas(x[21], x[22]); cas(x[23], x[24]);
}

// med = rank 25 of T(42) U g(7) = min(T[24], min_j max(T[17+j], g[6-j])).
DEV float select25(const float* T, const float* g) {
    float c0 = fmaxf(T[17], g[6]);
    float c1 = fmaxf(T[18], g[5]);
    float c2 = fmaxf(T[19], g[4]);
    float c3 = fmaxf(T[20], g[3]);
    float c4 = fmaxf(T[21], g[2]);
    float c5 = fmaxf(T[22], g[1]);
    float c6 = fmaxf(T[23], g[0]);
    float c7 = T[24];
    return fminf(fminf(fminf(c0, c1), fminf(c2, c3)),
                 fminf(fminf(c4, c5), fminf(c6, c7)));
}

DEV void load_pair14(const float4 (*pb)[5], int m, float* dst) {
    float4 v0 = pb[m][0], v1 = pb[m][1], v2 = pb[m][2], v3 = pb[m][3];
    dst[0]=v0.x;  dst[1]=v0.y;  dst[2]=v0.z;   dst[3]=v0.w;
    dst[4]=v1.x;  dst[5]=v1.y;  dst[6]=v1.z;   dst[7]=v1.w;
    dst[8]=v2.x;  dst[9]=v2.y;  dst[10]=v2.z;  dst[11]=v2.w;
    dst[12]=v3.x; dst[13]=v3.y;
}

// One CTA = one output row of one (b,c) plane; 256 threads, 257 tasks x 2 px.
__global__ __launch_bounds__(256, 6) void median7_kernel(const float* __restrict__ img,
                                                         float* __restrict__ out) {
    const int y     = blockIdx.x;        // 0..511
    const int plane = blockIdx.y;        // 0..23
    const int ch    = plane % 3;
    const float mean = c_mean[ch];
    const float sd   = c_std[ch];

    __shared__ float  srow[7][518];      // rows -> sorted columns (in place)
    __shared__ float4 pairbuf[260][5];   // pair m: sorted 14 in [m][0..3]

    const float* src = img + (size_t)plane * 262144;

    #pragma unroll
    for (int r = 0; r < 7; ++r) {
        int gy = y + r - 3;
        gy = (gy < 0) ? -gy : ((gy > 511) ? 1022 - gy : gy);
        const float* rp = src + gy * 512;
        for (int c = threadIdx.x; c < 518; c += 256) {
            int gx = c - 3;
            gx = (gx < 0) ? -gx : ((gx > 511) ? 1022 - gx : gx);
            float v = fmaf(rp[gx], sd, mean);
            srow[r][c] = fminf(fmaxf(v, 0.0f), 1.0f);
        }
    }
    __syncthreads();

    // Phase 1: task m owns smem columns 2m, 2m+1 exclusively (m < 259).
    for (int m = threadIdx.x; m < 259; m += 256) {
        float ca[7], cb[7], w[15];
        #pragma unroll
        for (int d = 0; d < 7; ++d) { ca[d] = srow[d][2 * m]; cb[d] = srow[d][2 * m + 1]; }
        sort7(ca); sort7(cb);
        #pragma unroll
        for (int d = 0; d < 7; ++d) { srow[d][2 * m] = ca[d]; srow[d][2 * m + 1] = cb[d]; }
        merge77(ca, cb, w);              // w[0..13] sorted
        pairbuf[m][0] = make_float4(w[0],  w[1],  w[2],  w[3]);
        pairbuf[m][1] = make_float4(w[4],  w[5],  w[6],  w[7]);
        pairbuf[m][2] = make_float4(w[8],  w[9],  w[10], w[11]);
        pairbuf[m][3] = make_float4(w[12], w[13], 0.0f,  0.0f);
    }
    __syncthreads();

    const float inv = 1.0f / sd;
    float* orow = out + (size_t)plane * 262144 + y * 512;

    // Phase 2: task u covers pixels at global cols (2u-1, 2u); both share the
    // pair triple {u, u+1, u+2}. u=0 emits only col 0; u=256 only col 511.
    for (int u = threadIdx.x; u <= 256; u += 256) {
        float x[46];
        load_pair14(pairbuf, u, x);
        load_pair14(pairbuf, u + 1, x + 16);
        mergeM(x);                       // x[3..24] = M[3..24]
        load_pair14(pairbuf, u + 2, x + 32);
        mergeT(x);                       // x[17..24] = T[17..24]

        {   // odd pixel: global col 2u-1, lone sorted column smem 2u-1
            int gc = (2 * u - 1 < 0) ? 0 : 2 * u - 1;
            float g[7];
            #pragma unroll
            for (int d = 0; d < 7; ++d) g[d] = srow[d][gc];
            float med = select25(x, g);
            if (u >= 1) orow[2 * u - 1] = (med - mean) * inv;
        }
        {   // even pixel: global col 2u, lone sorted column smem 2u+6
            int gc = (2 * u + 6 > 517) ? 517 : 2 * u + 6;
            float g[7];
            #pragma unroll
            for (int d = 0; d < 7; ++d) g[d] = srow[d][gc];
            float med = select25(x, g);
            if (u <= 255) orow[2 * u] = (med - mean) * inv;
        }
    }
}

extern "C" void kernel_launch(void* const* d_in, const int* in_sizes, int n_in,
                              void* d_out, int out_size) {
    const float* img  = (const float*)d_in[0];
    const float* mask = (const float*)d_in[1];
    float* out = (float*)d_out;
    const int img_elems  = in_sizes[0];
    const int mask_elems = in_sizes[1];

    dim3 grid(512, 24);
    median7_kernel<<<grid, 256>>>(img, out);
    cudaMemcpyAsync(out + img_elems, mask, (size_t)mask_elems * sizeof(float),
                    cudaMemcpyDeviceToDevice);
}